// round 14
// baseline (speedup 1.0000x reference)
#include <cuda_runtime.h>
#include <cuda_fp16.h>
#include <cstdint>

#define N_HEADS   16
#define HEAD_DIM  128
#define FF_DIM    512
#define D_MODEL   2048
#define TILE_M    128
#define FFC       64
#define NCH       (FF_DIM / FFC)   // 8
#define THREADS   512

// fp16 weights in B-fragment-major order (built once per launch)
__device__ __half g_W1f[N_HEADS * HEAD_DIM * FF_DIM];   // 2 MB
__device__ __half g_W2f[N_HEADS * FF_DIM * HEAD_DIM];   // 2 MB

// --------------------------------------------------------- SMEM layout ------
static constexpr int SM_H0  = 0;        // 16384
static constexpr int SM_H1  = 16384;    // 16384
static constexpr int SM_X   = 32768;    // 32768
static constexpr int SM_WA0 = 65536;    // 16384
static constexpr int SM_WA1 = 81920;    // 16384
static constexpr int SM_WB0 = 98304;    // 16384
static constexpr int SM_WB1 = 114688;   // 16384
static constexpr int SM_B1  = 131072;   // 256 x f16x2 bias pairs (1 KB)
static constexpr int SM_B2  = 133120;   // 128 f32
static constexpr int SMEM_TOTAL = 133632;

// ---------------------------------------------------------------- helpers ---
__device__ __forceinline__ uint32_t smem_u32(const void* p) {
    uint32_t a;
    asm("{ .reg .u64 t; cvta.to.shared.u64 t, %1; cvt.u32.u64 %0, t; }" : "=r"(a) : "l"(p));
    return a;
}
__device__ __forceinline__ uint32_t f2h2(float lo, float hi) {
    uint32_t r;
    asm("cvt.rn.f16x2.f32 %0, %1, %2;" : "=r"(r) : "f"(hi), "f"(lo));
    return r;
}
__device__ __forceinline__ uint32_t hadd2u(uint32_t a, uint32_t b) {
    uint32_t r;
    asm("add.f16x2 %0, %1, %2;" : "=r"(r) : "r"(a), "r"(b));
    return r;
}
__device__ __forceinline__ uint32_t hmax2z(uint32_t a) {
    uint32_t r;
    asm("max.f16x2 %0, %1, %2;" : "=r"(r) : "r"(a), "r"(0u));
    return r;
}
__device__ __forceinline__ void cp16(uint32_t s, const void* g) {
    asm volatile("cp.async.ca.shared.global [%0], [%1], 16;" :: "r"(s), "l"(g));
}
#define CP_COMMIT() asm volatile("cp.async.commit_group;" ::: "memory")
#define CP_WAIT1()  asm volatile("cp.async.wait_group 1;" ::: "memory")

#define BAR_SYNC(id)   asm volatile("bar.sync %0, 512;"   :: "r"(id) : "memory")
#define BAR_ARRIVE(id) asm volatile("bar.arrive %0, 512;" :: "r"(id) : "memory")
#define BAR_HALF(id)   asm volatile("bar.sync %0, 256;"   :: "r"(id) : "memory")

#define LDS128(r, addr) \
    asm volatile("ld.shared.v4.b32 {%0,%1,%2,%3}, [%4];" \
        : "=r"((r)[0]), "=r"((r)[1]), "=r"((r)[2]), "=r"((r)[3]) : "r"(addr))
#define STS128(addr, r) \
    asm volatile("st.shared.v4.b32 [%0], {%1,%2,%3,%4};" \
        :: "r"(addr), "r"((r)[0]), "r"((r)[1]), "r"((r)[2]), "r"((r)[3]) : "memory")

// f32-accum MMA (consumer)
__device__ __forceinline__ void mma16816(float* d, const uint32_t* a, const uint32_t* b) {
    asm("mma.sync.aligned.m16n8k16.row.col.f32.f16.f16.f32 "
        "{%0,%1,%2,%3}, {%4,%5,%6,%7}, {%8,%9}, {%0,%1,%2,%3};"
        : "+f"(d[0]), "+f"(d[1]), "+f"(d[2]), "+f"(d[3])
        : "r"(a[0]), "r"(a[1]), "r"(a[2]), "r"(a[3]), "r"(b[0]), "r"(b[1]));
}
// f16-accum MMA (producer) — D/C are 2 regs of f16x2
__device__ __forceinline__ void mma16816h(uint32_t* d, const uint32_t* a, const uint32_t* b) {
    asm("mma.sync.aligned.m16n8k16.row.col.f16.f16.f16.f16 "
        "{%0,%1}, {%2,%3,%4,%5}, {%6,%7}, {%0,%1};"
        : "+r"(d[0]), "+r"(d[1])
        : "r"(a[0]), "r"(a[1]), "r"(a[2]), "r"(a[3]), "r"(b[0]), "r"(b[1]));
}

// f16 MMA burst: 16 MMAs, dep distance 8 (khalf-0 sweep, then khalf-1 sweep)
__device__ __forceinline__ void burst1h(uint32_t hacc[2][4][2],
                                        const uint32_t ah[2][2][4],
                                        const uint32_t bf[4][4]) {
    #pragma unroll
    for (int nb = 0; nb < 4; ++nb) mma16816h(hacc[0][nb], ah[0][0], bf[nb]);
    #pragma unroll
    for (int nb = 0; nb < 4; ++nb) mma16816h(hacc[1][nb], ah[1][0], bf[nb]);
    #pragma unroll
    for (int nb = 0; nb < 4; ++nb) mma16816h(hacc[0][nb], ah[0][1], bf[nb] + 2);
    #pragma unroll
    for (int nb = 0; nb < 4; ++nb) mma16816h(hacc[1][nb], ah[1][1], bf[nb] + 2);
}
__device__ __forceinline__ void burst2(float (*a0)[4], float (*a1)[4],
                                       const uint32_t hf[2][2][4],
                                       const uint32_t bf[4][4]) {
    #pragma unroll
    for (int j = 0; j < 4; ++j) mma16816(a0[j], hf[0][0], bf[j]);
    #pragma unroll
    for (int j = 0; j < 4; ++j) mma16816(a1[j], hf[1][0], bf[j]);
    #pragma unroll
    for (int j = 0; j < 4; ++j) mma16816(a0[j], hf[0][1], bf[j] + 2);
    #pragma unroll
    for (int j = 0; j < 4; ++j) mma16816(a1[j], hf[1][1], bf[j] + 2);
}

// --------- weight -> fp16 B-fragment-major rearrange (coalesced, smem) ------
// Blocks 0..511: W1. Block handles (head, ks2, fc): 32 d-rows x 64 f-cols tile.
//   out block b = ((head*64 + nb)*4 + ks2)*32 + gg*4 + tt, 16B = 4 x f16x2 pairs
//   u[j] = halves (d0+off_j, d0+off_j+1), d0 = ks2*32 + 2*tt, off_j = (j>>1)*16 + (j&1)*8
// Blocks 512..767: W2. Block handles (head, ks2): 32 f-rows x 128 d-cols tile.
__global__ void __launch_bounds__(256) frag_kernel(const float* __restrict__ w1,
                                                   const float* __restrict__ w2) {
    __shared__ float tile[32][129];
    const int i = threadIdx.x;
    const int bid = blockIdx.x;

    if (bid < 512) {
        // ---- W1: src [head][d:128][f:512] ----
        const int head = bid >> 5;
        const int ks2  = (bid >> 3) & 3;
        const int fc   = bid & 7;
        const float* src = w1 + (size_t)head * 65536 + (size_t)(ks2 * 32) * 512 + fc * 64;
        #pragma unroll
        for (int k = 0; k < 2; ++k) {
            int seg = i + k * 256;                 // 512 float4 segs
            int row = seg >> 4, c4 = (seg & 15) << 2;
            float4 v = *reinterpret_cast<const float4*>(src + (size_t)row * 512 + c4);
            tile[row][c4 + 0] = v.x; tile[row][c4 + 1] = v.y;
            tile[row][c4 + 2] = v.z; tile[row][c4 + 3] = v.w;
        }
        __syncthreads();
        const int nb_l = i >> 5, lg = i & 31;      // nb_l 0..7 within chunk
        const int gg = lg >> 2, tt = lg & 3;
        const int fl = nb_l * 8 + gg;              // local f column 0..63
        const int d0 = tt * 2;                     // local d within 32-row tile
        uint32_t u[4];
        #pragma unroll
        for (int j = 0; j < 4; ++j) {
            int dl = d0 + (j >> 1) * 16 + (j & 1) * 8;
            u[j] = f2h2(tile[dl][fl], tile[dl + 1][fl]);
        }
        int b = ((head * 64 + (fc * 8 + nb_l)) * 4 + ks2) * 32 + lg;
        reinterpret_cast<uint4*>(g_W1f)[b] = make_uint4(u[0], u[1], u[2], u[3]);
    } else {
        // ---- W2: src [head][f:512][d:128] ----
        const int b2 = bid - 512;
        const int head = b2 >> 4;
        const int ks2  = b2 & 15;
        const float* src = w2 + (size_t)head * 65536 + (size_t)(ks2 * 32) * 128;
        #pragma unroll
        for (int k = 0; k < 4; ++k) {
            int seg = i + k * 256;                 // 1024 float4 segs
            int row = seg >> 5, c4 = (seg & 31) << 2;
            float4 v = *reinterpret_cast<const float4*>(src + (size_t)row * 128 + c4);
            tile[row][c4 + 0] = v.x; tile[row][c4 + 1] = v.y;
            tile[row][c4 + 2] = v.z; tile[row][c4 + 3] = v.w;
        }
        __syncthreads();
        #pragma unroll
        for (int k = 0; k < 2; ++k) {
            int v = i + k * 256;                   // 512 output blocks
            int nb = v >> 5, lg = v & 31;
            int gg = lg >> 2, tt = lg & 3;
            int d  = nb * 8 + gg;                  // column 0..127
            int f0 = tt * 2;                       // local f within 32-row tile
            uint32_t u[4];
            #pragma unroll
            for (int j = 0; j < 4; ++j) {
                int fl = f0 + (j >> 1) * 16 + (j & 1) * 8;
                u[j] = f2h2(tile[fl][d], tile[fl + 1][d]);
            }
            int b = ((head * 16 + nb) * 16 + ks2) * 32 + lg;
            reinterpret_cast<uint4*>(g_W2f)[b] = make_uint4(u[0], u[1], u[2], u[3]);
        }
    }
}

// ----------------------------------------------------------- main kernel ----
// Warps 0-7: producers (MMA1, f16 accum).  Warps 8-15: consumers (MMA2, f32).
// Barriers: 1/2 = H[p] full  (producer ARRIVE, consumer SYNC).
//           3/4 = H[p] free  (consumer ARRIVE, producer SYNC; skipped c<2).
//           5 = producer-only half.  6 = consumer-only half.
__global__ void __launch_bounds__(THREADS, 1)
ffn_kernel(const float* __restrict__ x, const float* __restrict__ b1,
           const float* __restrict__ b2, float* __restrict__ out) {
    extern __shared__ char smem[];
    const int tid  = threadIdx.x;
    const int lane = tid & 31;
    const int warp = tid >> 5;
    const int g    = lane >> 2;
    const int t    = lane & 3;
    const int w8   = warp & 7;
    const int wr   = w8 >> 1;        // 0..3 (32-row group)
    const int wc   = w8 & 1;         // 0..1 (col half)

    const int head = blockIdx.y;
    const int t0   = blockIdx.x * TILE_M;
    const uint32_t sb = smem_u32(smem);

    uint32_t* b1h2s = reinterpret_cast<uint32_t*>(smem + SM_B1);   // 256 f16x2 pairs
    float*    b2s   = reinterpret_cast<float*>(smem + SM_B2);

    const char* W1fb = (const char*)(g_W1f + (size_t)head * 65536);
    const char* W2fb = (const char*)(g_W2f + (size_t)head * 65536);

    // ---- prologue cp.async: producers load W1_0/W1_1, consumers W2_0/W2_1 ----
    if (warp < 8) {
        #pragma unroll
        for (int i = 0; i < 4; ++i) {
            int s = tid + i * 256;
            cp16(sb + SM_WA0 + s * 16, W1fb + s * 16);
        }
        CP_COMMIT();
        #pragma unroll
        for (int i = 0; i < 4; ++i) {
            int s = tid + i * 256;
            cp16(sb + SM_WA1 + s * 16, W1fb + 16384 + s * 16);
        }
        CP_COMMIT();
    } else {
        #pragma unroll
        for (int i = 0; i < 4; ++i) {
            int s = (tid - 256) + i * 256;
            int nb = s >> 6, r = s & 63;
            cp16(sb + SM_WB0 + s * 16, W2fb + nb * 8192 + r * 16);
        }
        CP_COMMIT();
        #pragma unroll
        for (int i = 0; i < 4; ++i) {
            int s = (tid - 256) + i * 256;
            int nb = s >> 6, r = s & 63;
            cp16(sb + SM_WB1 + s * 16, W2fb + nb * 8192 + 1024 + r * 16);
        }
        CP_COMMIT();
    }

    // ---- biases: b1 packed as f16x2 column pairs; b2 stays f32 ----
    if (tid < 256) {
        const float* bp = b1 + head * FF_DIM + 2 * tid;
        b1h2s[tid] = f2h2(bp[0], bp[1]);
    }
    if (tid < HEAD_DIM) b2s[tid] = b2[head * HEAD_DIM + tid];

    // ---- X tile: fp32 gmem -> fp16 A-fragment-major SMEM (persistent) ----
    #pragma unroll
    for (int i = 0; i < 8; ++i) {
        int u = tid + i * THREADS;            // 4096 float4 segs
        int row = u >> 5, c4 = (u & 31) << 2;
        float4 v = *reinterpret_cast<const float4*>(
            x + (size_t)(t0 + row) * D_MODEL + head * HEAD_DIM + c4);
        int rb = row >> 4, gg = row & 7, hm = (row >> 3) & 1;
        int ks = c4 >> 4, hk = (c4 >> 3) & 1, tA = (c4 & 7) >> 1;
        uint32_t base = (uint32_t)(SM_X + ((rb * 8 + ks) * 32) * 16);
        int ao = (hm * 2 + hk * 4) * 2;
        int ch0 = (gg * 4 + tA) ^ ks, ch1 = (gg * 4 + tA + 1) ^ ks;
        *reinterpret_cast<uint32_t*>(smem + base + ch0 * 16 + ao) = f2h2(v.x, v.y);
        *reinterpret_cast<uint32_t*>(smem + base + ch1 * 16 + ao) = f2h2(v.z, v.w);
    }
    __syncthreads();

    if (warp < 8) {
        // ============ PRODUCER: MMA1 = X @ W1 (f16 accum), relu -> H =========
        // X A-frags for ks2 0..1 live in registers; ks2 2..3 loaded per chunk.
        uint32_t xf[2][4][4];
        #pragma unroll
        for (int mi = 0; mi < 2; ++mi)
            #pragma unroll
            for (int ks = 0; ks < 4; ++ks) {
                int rb = wr * 2 + mi;
                LDS128(xf[mi][ks],
                       sb + SM_X + (uint32_t)(((rb * 8 + ks) * 32 + (lane ^ ks)) * 16));
            }

        for (int c = 0; c < NCH; ++c) {
            const uint32_t wa = sb + ((c & 1) ? SM_WA1 : SM_WA0);
            const uint32_t hp = sb + ((c & 1) ? SM_H1 : SM_H0);

            CP_WAIT1();
            BAR_HALF(5);                         // W1_c visible to all producers
            if (c >= 2) BAR_SYNC(3 + (c & 1));   // H[c&1] consumed (chunk c-2)

            // two k=64 f16 segment accumulators per frag (seg = ks2>>1)
            uint32_t hacc[2][2][4][2];           // [seg][mi][nb][reg]
            #pragma unroll
            for (int sg = 0; sg < 2; ++sg)
                #pragma unroll
                for (int mi = 0; mi < 2; ++mi)
                    #pragma unroll
                    for (int nb = 0; nb < 4; ++nb) {
                        hacc[sg][mi][nb][0] = 0u;
                        hacc[sg][mi][nb][1] = 0u;
                    }

            #pragma unroll
            for (int ks2 = 0; ks2 < 4; ++ks2) {
                uint32_t ah[2][2][4];
                #pragma unroll
                for (int mi = 0; mi < 2; ++mi)
                    #pragma unroll
                    for (int kp = 0; kp < 2; ++kp) {
                        if (ks2 < 2) {
                            #pragma unroll
                            for (int e = 0; e < 4; ++e)
                                ah[mi][kp][e] = xf[mi][ks2 * 2 + kp][e];
                        } else {
                            int rb = wr * 2 + mi, ks = ks2 * 2 + kp;
                            LDS128(ah[mi][kp],
                                sb + SM_X + (uint32_t)(((rb * 8 + ks) * 32 + (lane ^ ks)) * 16));
                        }
                    }
                uint32_t bf[4][4];
                #pragma unroll
                for (int nb = 0; nb < 4; ++nb) {
                    int nbL = wc * 4 + nb;
                    LDS128(bf[nb], wa + (uint32_t)(((nbL * 4 + ks2) * 32 + lane) * 16));
                }
                if (ks2 < 2) burst1h(hacc[0], ah, bf);
                else         burst1h(hacc[1], ah, bf);
            }
            BAR_HALF(5);                 // all producers done reading WA[c&1]

            // prefetch W1_{c+2} into the WA buffer just freed
            if (c + 2 < NCH) {
                #pragma unroll
                for (int i = 0; i < 4; ++i) {
                    int s = tid + i * 256;
                    cp16(wa + s * 16, W1fb + (c + 2) * 16384 + s * 16);
                }
            }
            CP_COMMIT();

            // combine segments + bias + relu entirely in f16x2 -> MMA2 A-frags
            uint32_t aH[2][2][4];
            #pragma unroll
            for (int mi = 0; mi < 2; ++mi)
                #pragma unroll
                for (int ni = 0; ni < 4; ++ni) {
                    uint32_t bp = b1h2s[c * 32 + wc * 16 + ni * 4 + t];
                    uint32_t r0 = hmax2z(hadd2u(hadd2u(hacc[0][mi][ni][0],
                                                       hacc[1][mi][ni][0]), bp));
                    uint32_t r1 = hmax2z(hadd2u(hadd2u(hacc[0][mi][ni][1],
                                                       hacc[1][mi][ni][1]), bp));
                    int ksl = ni >> 1, off = (ni & 1) * 2;
                    aH[mi][ksl][off]     = r0;   // row g   half
                    aH[mi][ksl][off + 1] = r1;   // row g+8 half
                }
            #pragma unroll
            for (int mi = 0; mi < 2; ++mi)
                #pragma unroll
                for (int ksl = 0; ksl < 2; ++ksl) {
                    int rb = wr * 2 + mi, ksH = wc * 2 + ksl;
                    STS128(hp + (uint32_t)(((rb * 4 + ksH) * 32 + lane) * 16), aH[mi][ksl]);
                }
            BAR_ARRIVE(1 + (c & 1));     // H[c&1] full (release; no block)
        }
        // producers done; exit
    } else {
        // ================= CONSUMER: MMA2 = H @ W2 -> out (f32 accum) ========
        float acc2[2][8][4];
        #pragma unroll
        for (int mi = 0; mi < 2; ++mi)
            #pragma unroll
            for (int ni = 0; ni < 8; ++ni)
                #pragma unroll
                for (int e = 0; e < 4; ++e) acc2[mi][ni][e] = 0.0f;

        for (int c = 0; c < NCH; ++c) {
            const uint32_t wb = sb + ((c & 1) ? SM_WB1 : SM_WB0);
            const uint32_t hp = sb + ((c & 1) ? SM_H1 : SM_H0);

            CP_WAIT1();
            BAR_HALF(6);                 // W2_c visible to all consumers
            BAR_SYNC(1 + (c & 1));       // H[c&1] full

            #pragma unroll
            for (int ks2 = 0; ks2 < 2; ++ks2) {
                uint32_t hf[2][2][4];
                #pragma unroll
                for (int mi = 0; mi < 2; ++mi)
                    #pragma unroll
                    for (int kp = 0; kp < 2; ++kp) {
                        int rb = wr * 2 + mi, ksH = ks2 * 2 + kp;
                        LDS128(hf[mi][kp],
                               hp + (uint32_t)(((rb * 4 + ksH) * 32 + lane) * 16));
                    }
                #pragma unroll
                for (int h4 = 0; h4 < 2; ++h4) {
                    uint32_t bf[4][4];
                    #pragma unroll
                    for (int j = 0; j < 4; ++j) {
                        int nb = wc * 8 + h4 * 4 + j;
                        LDS128(bf[j], wb + (uint32_t)(((nb * 2 + ks2) * 32 + lane) * 16));
                    }
                    burst2(&acc2[0][h4 * 4], &acc2[1][h4 * 4], hf, bf);
                }
            }
            BAR_ARRIVE(3 + (c & 1));     // H[c&1] free (non-blocking release)
            BAR_HALF(6);                 // all consumers done reading WB[c&1]

            // prefetch W2_{c+2} into the WB buffer just freed
            if (c + 2 < NCH) {
                #pragma unroll
                for (int i = 0; i < 4; ++i) {
                    int s = (tid - 256) + i * 256;
                    int nb = s >> 6, r = s & 63;
                    cp16(wb + s * 16, W2fb + nb * 8192 + (c + 2) * 1024 + r * 16);
                }
            }
            CP_COMMIT();
        }

        // ---- epilogue: acc2 + b2 -> gmem ----
        #pragma unroll
        for (int mi = 0; mi < 2; ++mi)
            #pragma unroll
            for (int ni = 0; ni < 8; ++ni) {
                int r1 = t0 + wr * 32 + mi * 16 + g;
                int cg = wc * 64 + ni * 8 + 2 * t;
                float2 v01, v23;
                v01.x = acc2[mi][ni][0] + b2s[cg];
                v01.y = acc2[mi][ni][1] + b2s[cg + 1];
                v23.x = acc2[mi][ni][2] + b2s[cg];
                v23.y = acc2[mi][ni][3] + b2s[cg + 1];
                *reinterpret_cast<float2*>(out + (size_t)r1 * D_MODEL + head * HEAD_DIM + cg) = v01;
                *reinterpret_cast<float2*>(out + (size_t)(r1 + 8) * D_MODEL + head * HEAD_DIM + cg) = v23;
            }
    }
}

// -------------------------------------------------------------- launch ------
extern "C" void kernel_launch(void* const* d_in, const int* in_sizes, int n_in,
                              void* d_out, int out_size) {
    const float* x  = (const float*)d_in[0];
    const float* W1 = (const float*)d_in[1];
    const float* b1 = (const float*)d_in[2];
    const float* W2 = (const float*)d_in[3];
    const float* b2 = (const float*)d_in[4];
    float* out = (float*)d_out;

    frag_kernel<<<768, 256>>>(W1, W2);   // 512 W1-tile blocks + 256 W2-tile blocks

    cudaFuncSetAttribute(ffn_kernel, cudaFuncAttributeMaxDynamicSharedMemorySize, SMEM_TOTAL);
    ffn_kernel<<<dim3(16384 / TILE_M, N_HEADS), THREADS, SMEM_TOTAL>>>(x, b1, b2, out);
}

// round 15
// speedup vs baseline: 1.0004x; 1.0004x over previous
#include <cuda_runtime.h>
#include <cuda_fp16.h>
#include <cstdint>

#define N_HEADS   16
#define HEAD_DIM  128
#define FF_DIM    512
#define D_MODEL   2048
#define TILE_M    128
#define FFC       64
#define NCH       (FF_DIM / FFC)   // 8
#define THREADS   512

// fp16 weights in B-fragment-major order (built once per launch)
__device__ __half g_W1f[N_HEADS * HEAD_DIM * FF_DIM];   // 2 MB
__device__ __half g_W2f[N_HEADS * FF_DIM * HEAD_DIM];   // 2 MB

// --------------------------------------------------------- SMEM layout ------
static constexpr int SM_H0  = 0;        // 16384
static constexpr int SM_H1  = 16384;    // 16384
static constexpr int SM_X   = 32768;    // 32768
static constexpr int SM_WA0 = 65536;    // 16384
static constexpr int SM_WA1 = 81920;    // 16384
static constexpr int SM_WB0 = 98304;    // 16384
static constexpr int SM_WB1 = 114688;   // 16384
static constexpr int SM_B1  = 131072;   // 256 x f16x2 bias pairs (1 KB)
static constexpr int SM_B2  = 133120;   // 128 f32
static constexpr int SMEM_TOTAL = 133632;

// ---------------------------------------------------------------- helpers ---
__device__ __forceinline__ uint32_t smem_u32(const void* p) {
    uint32_t a;
    asm("{ .reg .u64 t; cvta.to.shared.u64 t, %1; cvt.u32.u64 %0, t; }" : "=r"(a) : "l"(p));
    return a;
}
__device__ __forceinline__ uint32_t f2h2(float lo, float hi) {
    uint32_t r;
    asm("cvt.rn.f16x2.f32 %0, %1, %2;" : "=r"(r) : "f"(hi), "f"(lo));
    return r;
}
__device__ __forceinline__ uint32_t hadd2u(uint32_t a, uint32_t b) {
    uint32_t r;
    asm("add.f16x2 %0, %1, %2;" : "=r"(r) : "r"(a), "r"(b));
    return r;
}
__device__ __forceinline__ uint32_t hmax2z(uint32_t a) {
    uint32_t r;
    asm("max.f16x2 %0, %1, %2;" : "=r"(r) : "r"(a), "r"(0u));
    return r;
}
__device__ __forceinline__ void cp16(uint32_t s, const void* g) {
    asm volatile("cp.async.ca.shared.global [%0], [%1], 16;" :: "r"(s), "l"(g));
}
#define CP_COMMIT() asm volatile("cp.async.commit_group;" ::: "memory")
#define CP_WAIT1()  asm volatile("cp.async.wait_group 1;" ::: "memory")

#define BAR_SYNC(id)   asm volatile("bar.sync %0, 512;"   :: "r"(id) : "memory")
#define BAR_ARRIVE(id) asm volatile("bar.arrive %0, 512;" :: "r"(id) : "memory")
#define BAR_HALF(id)   asm volatile("bar.sync %0, 256;"   :: "r"(id) : "memory")

#define LDS128(r, addr) \
    asm volatile("ld.shared.v4.b32 {%0,%1,%2,%3}, [%4];" \
        : "=r"((r)[0]), "=r"((r)[1]), "=r"((r)[2]), "=r"((r)[3]) : "r"(addr))
#define STS128(addr, r) \
    asm volatile("st.shared.v4.b32 [%0], {%1,%2,%3,%4};" \
        :: "r"(addr), "r"((r)[0]), "r"((r)[1]), "r"((r)[2]), "r"((r)[3]) : "memory")

// f32-accum MMA (consumer)
__device__ __forceinline__ void mma16816(float* d, const uint32_t* a, const uint32_t* b) {
    asm("mma.sync.aligned.m16n8k16.row.col.f32.f16.f16.f32 "
        "{%0,%1,%2,%3}, {%4,%5,%6,%7}, {%8,%9}, {%0,%1,%2,%3};"
        : "+f"(d[0]), "+f"(d[1]), "+f"(d[2]), "+f"(d[3])
        : "r"(a[0]), "r"(a[1]), "r"(a[2]), "r"(a[3]), "r"(b[0]), "r"(b[1]));
}
// f16-accum MMA (producer) — D/C are 2 regs of f16x2
__device__ __forceinline__ void mma16816h(uint32_t* d, const uint32_t* a, const uint32_t* b) {
    asm("mma.sync.aligned.m16n8k16.row.col.f16.f16.f16.f16 "
        "{%0,%1}, {%2,%3,%4,%5}, {%6,%7}, {%0,%1};"
        : "+r"(d[0]), "+r"(d[1])
        : "r"(a[0]), "r"(a[1]), "r"(a[2]), "r"(a[3]), "r"(b[0]), "r"(b[1]));
}

// f16 MMA burst: 16 MMAs, dep distance 8 (khalf-0 sweep, then khalf-1 sweep)
__device__ __forceinline__ void burst1h(uint32_t hacc[2][4][2],
                                        const uint32_t ah[2][2][4],
                                        const uint32_t bf[4][4]) {
    #pragma unroll
    for (int nb = 0; nb < 4; ++nb) mma16816h(hacc[0][nb], ah[0][0], bf[nb]);
    #pragma unroll
    for (int nb = 0; nb < 4; ++nb) mma16816h(hacc[1][nb], ah[1][0], bf[nb]);
    #pragma unroll
    for (int nb = 0; nb < 4; ++nb) mma16816h(hacc[0][nb], ah[0][1], bf[nb] + 2);
    #pragma unroll
    for (int nb = 0; nb < 4; ++nb) mma16816h(hacc[1][nb], ah[1][1], bf[nb] + 2);
}
__device__ __forceinline__ void burst2(float (*a0)[4], float (*a1)[4],
                                       const uint32_t hf[2][2][4],
                                       const uint32_t bf[4][4]) {
    #pragma unroll
    for (int j = 0; j < 4; ++j) mma16816(a0[j], hf[0][0], bf[j]);
    #pragma unroll
    for (int j = 0; j < 4; ++j) mma16816(a1[j], hf[1][0], bf[j]);
    #pragma unroll
    for (int j = 0; j < 4; ++j) mma16816(a0[j], hf[0][1], bf[j] + 2);
    #pragma unroll
    for (int j = 0; j < 4; ++j) mma16816(a1[j], hf[1][1], bf[j] + 2);
}

// ------------------------------ weight -> fp16 B-fragment-major rearrange ---
__global__ void frag_kernel(const float* __restrict__ w1, const float* __restrict__ w2) {
    int b = blockIdx.x * blockDim.x + threadIdx.x;   // 0 .. 131071
    {   // W1: src [head][d:128][f:512]
        int tt = b & 3, gg = (b >> 2) & 7, ks2 = (b >> 5) & 3;
        int nb = (b >> 7) & 63, head = b >> 13;
        const float* s = w1 + (size_t)head * 65536 + nb * 8 + gg;
        int dbase = ks2 * 32 + tt * 2;
        uint32_t u[4];
        #pragma unroll
        for (int j = 0; j < 4; ++j) {
            int d = dbase + (j >> 1) * 16 + (j & 1) * 8;
            u[j] = f2h2(s[(size_t)d * 512], s[(size_t)(d + 1) * 512]);
        }
        reinterpret_cast<uint4*>(g_W1f)[b] = make_uint4(u[0], u[1], u[2], u[3]);
    }
    {   // W2: src [head][f:512][d:128]
        int tt = b & 3, gg = (b >> 2) & 7, ks2 = (b >> 5) & 15;
        int nb = (b >> 9) & 15, head = b >> 13;
        const float* s = w2 + (size_t)head * 65536 + nb * 8 + gg;
        int fbase = ks2 * 32 + tt * 2;
        uint32_t u[4];
        #pragma unroll
        for (int j = 0; j < 4; ++j) {
            int f = fbase + (j >> 1) * 16 + (j & 1) * 8;
            u[j] = f2h2(s[(size_t)f * 128], s[(size_t)(f + 1) * 128]);
        }
        reinterpret_cast<uint4*>(g_W2f)[b] = make_uint4(u[0], u[1], u[2], u[3]);
    }
}

// ----------------------------------------------------------- main kernel ----
// Warps 0-7: producers (MMA1, f16 accum).  Warps 8-15: consumers (MMA2, f32).
// Barriers: 1/2 = H[p] full  (producer ARRIVE, consumer SYNC).
//           3/4 = H[p] free  (consumer ARRIVE, producer SYNC; skipped c<2).
//           5 = producer-only half.  6 = consumer-only half.
__global__ void __launch_bounds__(THREADS, 1)
ffn_kernel(const float* __restrict__ x, const float* __restrict__ b1,
           const float* __restrict__ b2, float* __restrict__ out) {
    extern __shared__ char smem[];
    const int tid  = threadIdx.x;
    const int lane = tid & 31;
    const int warp = tid >> 5;
    const int g    = lane >> 2;
    const int t    = lane & 3;
    const int w8   = warp & 7;
    const int wr   = w8 >> 1;        // 0..3 (32-row group)
    const int wc   = w8 & 1;         // 0..1 (col half)

    const int head = blockIdx.y;
    const int t0   = blockIdx.x * TILE_M;
    const uint32_t sb = smem_u32(smem);

    uint32_t* b1h2s = reinterpret_cast<uint32_t*>(smem + SM_B1);   // 256 f16x2 pairs
    float*    b2s   = reinterpret_cast<float*>(smem + SM_B2);

    const char* W1fb = (const char*)(g_W1f + (size_t)head * 65536);
    const char* W2fb = (const char*)(g_W2f + (size_t)head * 65536);

    // ---- prologue cp.async: producers load W1_0/W1_1, consumers W2_0/W2_1 ----
    if (warp < 8) {
        #pragma unroll
        for (int i = 0; i < 4; ++i) {
            int s = tid + i * 256;
            cp16(sb + SM_WA0 + s * 16, W1fb + s * 16);
        }
        CP_COMMIT();
        #pragma unroll
        for (int i = 0; i < 4; ++i) {
            int s = tid + i * 256;
            cp16(sb + SM_WA1 + s * 16, W1fb + 16384 + s * 16);
        }
        CP_COMMIT();
    } else {
        #pragma unroll
        for (int i = 0; i < 4; ++i) {
            int s = (tid - 256) + i * 256;
            int nb = s >> 6, r = s & 63;
            cp16(sb + SM_WB0 + s * 16, W2fb + nb * 8192 + r * 16);
        }
        CP_COMMIT();
        #pragma unroll
        for (int i = 0; i < 4; ++i) {
            int s = (tid - 256) + i * 256;
            int nb = s >> 6, r = s & 63;
            cp16(sb + SM_WB1 + s * 16, W2fb + nb * 8192 + 1024 + r * 16);
        }
        CP_COMMIT();
    }

    // ---- biases: b1 packed as f16x2 column pairs; b2 stays f32 ----
    if (tid < 256) {
        const float* bp = b1 + head * FF_DIM + 2 * tid;
        b1h2s[tid] = f2h2(bp[0], bp[1]);
    }
    if (tid < HEAD_DIM) b2s[tid] = b2[head * HEAD_DIM + tid];

    // ---- X tile: fp32 gmem -> fp16 A-fragment-major SMEM (persistent) ----
    #pragma unroll
    for (int i = 0; i < 8; ++i) {
        int u = tid + i * THREADS;            // 4096 float4 segs
        int row = u >> 5, c4 = (u & 31) << 2;
        float4 v = *reinterpret_cast<const float4*>(
            x + (size_t)(t0 + row) * D_MODEL + head * HEAD_DIM + c4);
        int rb = row >> 4, gg = row & 7, hm = (row >> 3) & 1;
        int ks = c4 >> 4, hk = (c4 >> 3) & 1, tA = (c4 & 7) >> 1;
        uint32_t base = (uint32_t)(SM_X + ((rb * 8 + ks) * 32) * 16);
        int ao = (hm * 2 + hk * 4) * 2;
        int ch0 = (gg * 4 + tA) ^ ks, ch1 = (gg * 4 + tA + 1) ^ ks;
        *reinterpret_cast<uint32_t*>(smem + base + ch0 * 16 + ao) = f2h2(v.x, v.y);
        *reinterpret_cast<uint32_t*>(smem + base + ch1 * 16 + ao) = f2h2(v.z, v.w);
    }
    __syncthreads();

    if (warp < 8) {
        // ============ PRODUCER: MMA1 = X @ W1 (f16 accum), relu -> H =========
        // X A-frags for ks2 0..1 live in registers; ks2 2..3 loaded per chunk.
        uint32_t xf[2][4][4];
        #pragma unroll
        for (int mi = 0; mi < 2; ++mi)
            #pragma unroll
            for (int ks = 0; ks < 4; ++ks) {
                int rb = wr * 2 + mi;
                LDS128(xf[mi][ks],
                       sb + SM_X + (uint32_t)(((rb * 8 + ks) * 32 + (lane ^ ks)) * 16));
            }

        for (int c = 0; c < NCH; ++c) {
            const uint32_t wa = sb + ((c & 1) ? SM_WA1 : SM_WA0);
            const uint32_t hp = sb + ((c & 1) ? SM_H1 : SM_H0);

            CP_WAIT1();
            BAR_HALF(5);                         // W1_c visible to all producers
            if (c >= 2) BAR_SYNC(3 + (c & 1));   // H[c&1] consumed (chunk c-2)

            // two k=64 f16 segment accumulators per frag (seg = ks2>>1)
            uint32_t hacc[2][2][4][2];           // [seg][mi][nb][reg]
            #pragma unroll
            for (int sg = 0; sg < 2; ++sg)
                #pragma unroll
                for (int mi = 0; mi < 2; ++mi)
                    #pragma unroll
                    for (int nb = 0; nb < 4; ++nb) {
                        hacc[sg][mi][nb][0] = 0u;
                        hacc[sg][mi][nb][1] = 0u;
                    }

            #pragma unroll
            for (int ks2 = 0; ks2 < 4; ++ks2) {
                uint32_t ah[2][2][4];
                #pragma unroll
                for (int mi = 0; mi < 2; ++mi)
                    #pragma unroll
                    for (int kp = 0; kp < 2; ++kp) {
                        if (ks2 < 2) {
                            #pragma unroll
                            for (int e = 0; e < 4; ++e)
                                ah[mi][kp][e] = xf[mi][ks2 * 2 + kp][e];
                        } else {
                            int rb = wr * 2 + mi, ks = ks2 * 2 + kp;
                            LDS128(ah[mi][kp],
                                sb + SM_X + (uint32_t)(((rb * 8 + ks) * 32 + (lane ^ ks)) * 16));
                        }
                    }
                uint32_t bf[4][4];
                #pragma unroll
                for (int nb = 0; nb < 4; ++nb) {
                    int nbL = wc * 4 + nb;
                    LDS128(bf[nb], wa + (uint32_t)(((nbL * 4 + ks2) * 32 + lane) * 16));
                }
                if (ks2 < 2) burst1h(hacc[0], ah, bf);
                else         burst1h(hacc[1], ah, bf);
            }
            BAR_HALF(5);                 // all producers done reading WA[c&1]

            // prefetch W1_{c+2} into the WA buffer just freed
            if (c + 2 < NCH) {
                #pragma unroll
                for (int i = 0; i < 4; ++i) {
                    int s = tid + i * 256;
                    cp16(wa + s * 16, W1fb + (c + 2) * 16384 + s * 16);
                }
            }
            CP_COMMIT();

            // combine segments + bias + relu entirely in f16x2 -> MMA2 A-frags
            uint32_t aH[2][2][4];
            #pragma unroll
            for (int mi = 0; mi < 2; ++mi)
                #pragma unroll
                for (int ni = 0; ni < 4; ++ni) {
                    uint32_t bp = b1h2s[c * 32 + wc * 16 + ni * 4 + t];
                    uint32_t r0 = hmax2z(hadd2u(hadd2u(hacc[0][mi][ni][0],
                                                       hacc[1][mi][ni][0]), bp));
                    uint32_t r1 = hmax2z(hadd2u(hadd2u(hacc[0][mi][ni][1],
                                                       hacc[1][mi][ni][1]), bp));
                    int ksl = ni >> 1, off = (ni & 1) * 2;
                    aH[mi][ksl][off]     = r0;   // row g   half
                    aH[mi][ksl][off + 1] = r1;   // row g+8 half
                }
            #pragma unroll
            for (int mi = 0; mi < 2; ++mi)
                #pragma unroll
                for (int ksl = 0; ksl < 2; ++ksl) {
                    int rb = wr * 2 + mi, ksH = wc * 2 + ksl;
                    STS128(hp + (uint32_t)(((rb * 4 + ksH) * 32 + lane) * 16), aH[mi][ksl]);
                }
            BAR_ARRIVE(1 + (c & 1));     // H[c&1] full (release; no block)
        }
        // producers done; exit
    } else {
        // ================= CONSUMER: MMA2 = H @ W2 -> out (f32 accum) ========
        float acc2[2][8][4];
        #pragma unroll
        for (int mi = 0; mi < 2; ++mi)
            #pragma unroll
            for (int ni = 0; ni < 8; ++ni)
                #pragma unroll
                for (int e = 0; e < 4; ++e) acc2[mi][ni][e] = 0.0f;

        for (int c = 0; c < NCH; ++c) {
            const uint32_t wb = sb + ((c & 1) ? SM_WB1 : SM_WB0);
            const uint32_t hp = sb + ((c & 1) ? SM_H1 : SM_H0);

            CP_WAIT1();
            BAR_HALF(6);                 // W2_c visible to all consumers
            BAR_SYNC(1 + (c & 1));       // H[c&1] full

            #pragma unroll
            for (int ks2 = 0; ks2 < 2; ++ks2) {
                uint32_t hf[2][2][4];
                #pragma unroll
                for (int mi = 0; mi < 2; ++mi)
                    #pragma unroll
                    for (int kp = 0; kp < 2; ++kp) {
                        int rb = wr * 2 + mi, ksH = ks2 * 2 + kp;
                        LDS128(hf[mi][kp],
                               hp + (uint32_t)(((rb * 4 + ksH) * 32 + lane) * 16));
                    }
                #pragma unroll
                for (int h4 = 0; h4 < 2; ++h4) {
                    uint32_t bf[4][4];
                    #pragma unroll
                    for (int j = 0; j < 4; ++j) {
                        int nb = wc * 8 + h4 * 4 + j;
                        LDS128(bf[j], wb + (uint32_t)(((nb * 2 + ks2) * 32 + lane) * 16));
                    }
                    burst2(&acc2[0][h4 * 4], &acc2[1][h4 * 4], hf, bf);
                }
            }
            BAR_ARRIVE(3 + (c & 1));     // H[c&1] free (non-blocking release)
            BAR_HALF(6);                 // all consumers done reading WB[c&1]

            // prefetch W2_{c+2} into the WB buffer just freed
            if (c + 2 < NCH) {
                #pragma unroll
                for (int i = 0; i < 4; ++i) {
                    int s = (tid - 256) + i * 256;
                    int nb = s >> 6, r = s & 63;
                    cp16(wb + s * 16, W2fb + nb * 8192 + (c + 2) * 1024 + r * 16);
                }
            }
            CP_COMMIT();
        }

        // ---- epilogue: acc2 + b2 -> gmem ----
        #pragma unroll
        for (int mi = 0; mi < 2; ++mi)
            #pragma unroll
            for (int ni = 0; ni < 8; ++ni) {
                int r1 = t0 + wr * 32 + mi * 16 + g;
                int cg = wc * 64 + ni * 8 + 2 * t;
                float2 v01, v23;
                v01.x = acc2[mi][ni][0] + b2s[cg];
                v01.y = acc2[mi][ni][1] + b2s[cg + 1];
                v23.x = acc2[mi][ni][2] + b2s[cg];
                v23.y = acc2[mi][ni][3] + b2s[cg + 1];
                *reinterpret_cast<float2*>(out + (size_t)r1 * D_MODEL + head * HEAD_DIM + cg) = v01;
                *reinterpret_cast<float2*>(out + (size_t)(r1 + 8) * D_MODEL + head * HEAD_DIM + cg) = v23;
            }
    }
}

// -------------------------------------------------------------- launch ------
extern "C" void kernel_launch(void* const* d_in, const int* in_sizes, int n_in,
                              void* d_out, int out_size) {
    const float* x  = (const float*)d_in[0];
    const float* W1 = (const float*)d_in[1];
    const float* b1 = (const float*)d_in[2];
    const float* W2 = (const float*)d_in[3];
    const float* b2 = (const float*)d_in[4];
    float* out = (float*)d_out;

    frag_kernel<<<512, 256>>>(W1, W2);   // 131072 threads, one 16B block each

    cudaFuncSetAttribute(ffn_kernel, cudaFuncAttributeMaxDynamicSharedMemorySize, SMEM_TOTAL);
    ffn_kernel<<<dim3(16384 / TILE_M, N_HEADS), THREADS, SMEM_TOTAL>>>(x, b1, b2, out);
}

// round 16
// speedup vs baseline: 1.0008x; 1.0004x over previous
#include <cuda_runtime.h>
#include <cuda_fp16.h>
#include <cstdint>

#define N_HEADS   16
#define HEAD_DIM  128
#define FF_DIM    512
#define D_MODEL   2048
#define TILE_M    128
#define FFC       64
#define NCH       (FF_DIM / FFC)   // 8
#define THREADS   512

// fp16 weights in B-fragment-major order (built once per launch)
__device__ __half g_W1f[N_HEADS * HEAD_DIM * FF_DIM];   // 2 MB
__device__ __half g_W2f[N_HEADS * FF_DIM * HEAD_DIM];   // 2 MB

// --------------------------------------------------------- SMEM layout ------
static constexpr int SM_H0  = 0;        // 16384
static constexpr int SM_H1  = 16384;    // 16384
static constexpr int SM_X   = 32768;    // 32768
static constexpr int SM_WA0 = 65536;    // 16384
static constexpr int SM_WA1 = 81920;    // 16384
static constexpr int SM_WB0 = 98304;    // 16384
static constexpr int SM_WB1 = 114688;   // 16384
static constexpr int SM_B1  = 131072;   // 256 x f16x2 bias pairs (1 KB)
static constexpr int SM_B2  = 133120;   // 128 f32
static constexpr int SMEM_TOTAL = 133632;

// ---------------------------------------------------------------- helpers ---
__device__ __forceinline__ uint32_t smem_u32(const void* p) {
    uint32_t a;
    asm("{ .reg .u64 t; cvta.to.shared.u64 t, %1; cvt.u32.u64 %0, t; }" : "=r"(a) : "l"(p));
    return a;
}
__device__ __forceinline__ uint32_t f2h2(float lo, float hi) {
    uint32_t r;
    asm("cvt.rn.f16x2.f32 %0, %1, %2;" : "=r"(r) : "f"(hi), "f"(lo));
    return r;
}
__device__ __forceinline__ uint32_t hadd2u(uint32_t a, uint32_t b) {
    uint32_t r;
    asm("add.f16x2 %0, %1, %2;" : "=r"(r) : "r"(a), "r"(b));
    return r;
}
__device__ __forceinline__ uint32_t hmax2z(uint32_t a) {
    uint32_t r;
    asm("max.f16x2 %0, %1, %2;" : "=r"(r) : "r"(a), "r"(0u));
    return r;
}
__device__ __forceinline__ void cp16(uint32_t s, const void* g) {
    asm volatile("cp.async.ca.shared.global [%0], [%1], 16;" :: "r"(s), "l"(g));
}
#define CP_COMMIT() asm volatile("cp.async.commit_group;" ::: "memory")
#define CP_WAIT1()  asm volatile("cp.async.wait_group 1;" ::: "memory")

#define BAR_SYNC(id)   asm volatile("bar.sync %0, 512;"   :: "r"(id) : "memory")
#define BAR_ARRIVE(id) asm volatile("bar.arrive %0, 512;" :: "r"(id) : "memory")
#define BAR_HALF(id)   asm volatile("bar.sync %0, 256;"   :: "r"(id) : "memory")

#define LDS128(r, addr) \
    asm volatile("ld.shared.v4.b32 {%0,%1,%2,%3}, [%4];" \
        : "=r"((r)[0]), "=r"((r)[1]), "=r"((r)[2]), "=r"((r)[3]) : "r"(addr))
#define STS128(addr, r) \
    asm volatile("st.shared.v4.b32 [%0], {%1,%2,%3,%4};" \
        :: "r"(addr), "r"((r)[0]), "r"((r)[1]), "r"((r)[2]), "r"((r)[3]) : "memory")

// f32-accum MMA (consumer)
__device__ __forceinline__ void mma16816(float* d, const uint32_t* a, const uint32_t* b) {
    asm("mma.sync.aligned.m16n8k16.row.col.f32.f16.f16.f32 "
        "{%0,%1,%2,%3}, {%4,%5,%6,%7}, {%8,%9}, {%0,%1,%2,%3};"
        : "+f"(d[0]), "+f"(d[1]), "+f"(d[2]), "+f"(d[3])
        : "r"(a[0]), "r"(a[1]), "r"(a[2]), "r"(a[3]), "r"(b[0]), "r"(b[1]));
}
// f16-accum MMA (producer) — D/C are 2 regs of f16x2
__device__ __forceinline__ void mma16816h(uint32_t* d, const uint32_t* a, const uint32_t* b) {
    asm("mma.sync.aligned.m16n8k16.row.col.f16.f16.f16.f16 "
        "{%0,%1}, {%2,%3,%4,%5}, {%6,%7}, {%0,%1};"
        : "+r"(d[0]), "+r"(d[1])
        : "r"(a[0]), "r"(a[1]), "r"(a[2]), "r"(a[3]), "r"(b[0]), "r"(b[1]));
}

// f16 MMA burst: 16 MMAs, dep distance 8 (khalf-0 sweep, then khalf-1 sweep)
__device__ __forceinline__ void burst1h(uint32_t hacc[2][4][2],
                                        const uint32_t ah[2][2][4],
                                        const uint32_t bf[4][4]) {
    #pragma unroll
    for (int nb = 0; nb < 4; ++nb) mma16816h(hacc[0][nb], ah[0][0], bf[nb]);
    #pragma unroll
    for (int nb = 0; nb < 4; ++nb) mma16816h(hacc[1][nb], ah[1][0], bf[nb]);
    #pragma unroll
    for (int nb = 0; nb < 4; ++nb) mma16816h(hacc[0][nb], ah[0][1], bf[nb] + 2);
    #pragma unroll
    for (int nb = 0; nb < 4; ++nb) mma16816h(hacc[1][nb], ah[1][1], bf[nb] + 2);
}
__device__ __forceinline__ void burst2(float (*a0)[4], float (*a1)[4],
                                       const uint32_t hf[2][2][4],
                                       const uint32_t bf[4][4]) {
    #pragma unroll
    for (int j = 0; j < 4; ++j) mma16816(a0[j], hf[0][0], bf[j]);
    #pragma unroll
    for (int j = 0; j < 4; ++j) mma16816(a1[j], hf[1][0], bf[j]);
    #pragma unroll
    for (int j = 0; j < 4; ++j) mma16816(a0[j], hf[0][1], bf[j] + 2);
    #pragma unroll
    for (int j = 0; j < 4; ++j) mma16816(a1[j], hf[1][1], bf[j] + 2);
}

// ------------------------------ weight -> fp16 B-fragment-major rearrange ---
__global__ void frag_kernel(const float* __restrict__ w1, const float* __restrict__ w2) {
    int b = blockIdx.x * blockDim.x + threadIdx.x;   // 0 .. 131071
    {   // W1: src [head][d:128][f:512]
        int tt = b & 3, gg = (b >> 2) & 7, ks2 = (b >> 5) & 3;
        int nb = (b >> 7) & 63, head = b >> 13;
        const float* s = w1 + (size_t)head * 65536 + nb * 8 + gg;
        int dbase = ks2 * 32 + tt * 2;
        uint32_t u[4];
        #pragma unroll
        for (int j = 0; j < 4; ++j) {
            int d = dbase + (j >> 1) * 16 + (j & 1) * 8;
            u[j] = f2h2(s[(size_t)d * 512], s[(size_t)(d + 1) * 512]);
        }
        reinterpret_cast<uint4*>(g_W1f)[b] = make_uint4(u[0], u[1], u[2], u[3]);
    }
    {   // W2: src [head][f:512][d:128]
        int tt = b & 3, gg = (b >> 2) & 7, ks2 = (b >> 5) & 15;
        int nb = (b >> 9) & 15, head = b >> 13;
        const float* s = w2 + (size_t)head * 65536 + nb * 8 + gg;
        int fbase = ks2 * 32 + tt * 2;
        uint32_t u[4];
        #pragma unroll
        for (int j = 0; j < 4; ++j) {
            int f = fbase + (j >> 1) * 16 + (j & 1) * 8;
            u[j] = f2h2(s[(size_t)f * 128], s[(size_t)(f + 1) * 128]);
        }
        reinterpret_cast<uint4*>(g_W2f)[b] = make_uint4(u[0], u[1], u[2], u[3]);
    }
}

// ----------------------------------------------------------- main kernel ----
// Warps 0-7: producers (MMA1, f16 accum).  Warps 8-15: consumers (MMA2, f32).
// Barriers: 1/2 = H[p] full  (producer ARRIVE, consumer SYNC).
//           3/4 = H[p] free  (consumer ARRIVE, producer SYNC; skipped c<2).
//           5 = producer-only half.  6 = consumer-only half.
__global__ void __launch_bounds__(THREADS, 1)
ffn_kernel(const float* __restrict__ x, const float* __restrict__ b1,
           const float* __restrict__ b2, float* __restrict__ out) {
    extern __shared__ char smem[];
    const int tid  = threadIdx.x;
    const int lane = tid & 31;
    const int warp = tid >> 5;
    const int g    = lane >> 2;
    const int t    = lane & 3;
    const int w8   = warp & 7;
    const int wr   = w8 >> 1;        // 0..3 (32-row group)
    const int wc   = w8 & 1;         // 0..1 (col half)

    const int head = blockIdx.y;
    const int t0   = blockIdx.x * TILE_M;
    const uint32_t sb = smem_u32(smem);

    uint32_t* b1h2s = reinterpret_cast<uint32_t*>(smem + SM_B1);   // 256 f16x2 pairs
    float*    b2s   = reinterpret_cast<float*>(smem + SM_B2);

    const char* W1fb = (const char*)(g_W1f + (size_t)head * 65536);
    const char* W2fb = (const char*)(g_W2f + (size_t)head * 65536);

    // ---- prologue cp.async: producers load W1_0/W1_1, consumers W2_0/W2_1 ----
    if (warp < 8) {
        #pragma unroll
        for (int i = 0; i < 4; ++i) {
            int s = tid + i * 256;
            cp16(sb + SM_WA0 + s * 16, W1fb + s * 16);
        }
        CP_COMMIT();
        #pragma unroll
        for (int i = 0; i < 4; ++i) {
            int s = tid + i * 256;
            cp16(sb + SM_WA1 + s * 16, W1fb + 16384 + s * 16);
        }
        CP_COMMIT();
    } else {
        #pragma unroll
        for (int i = 0; i < 4; ++i) {
            int s = (tid - 256) + i * 256;
            int nb = s >> 6, r = s & 63;
            cp16(sb + SM_WB0 + s * 16, W2fb + nb * 8192 + r * 16);
        }
        CP_COMMIT();
        #pragma unroll
        for (int i = 0; i < 4; ++i) {
            int s = (tid - 256) + i * 256;
            int nb = s >> 6, r = s & 63;
            cp16(sb + SM_WB1 + s * 16, W2fb + nb * 8192 + 1024 + r * 16);
        }
        CP_COMMIT();
    }

    // ---- biases: b1 packed as f16x2 column pairs; b2 stays f32 ----
    if (tid < 256) {
        const float* bp = b1 + head * FF_DIM + 2 * tid;
        b1h2s[tid] = f2h2(bp[0], bp[1]);
    }
    if (tid < HEAD_DIM) b2s[tid] = b2[head * HEAD_DIM + tid];

    // ---- X tile: fp32 gmem -> fp16 A-fragment-major SMEM (persistent) ----
    #pragma unroll
    for (int i = 0; i < 8; ++i) {
        int u = tid + i * THREADS;            // 4096 float4 segs
        int row = u >> 5, c4 = (u & 31) << 2;
        float4 v = *reinterpret_cast<const float4*>(
            x + (size_t)(t0 + row) * D_MODEL + head * HEAD_DIM + c4);
        int rb = row >> 4, gg = row & 7, hm = (row >> 3) & 1;
        int ks = c4 >> 4, hk = (c4 >> 3) & 1, tA = (c4 & 7) >> 1;
        uint32_t base = (uint32_t)(SM_X + ((rb * 8 + ks) * 32) * 16);
        int ao = (hm * 2 + hk * 4) * 2;
        int ch0 = (gg * 4 + tA) ^ ks, ch1 = (gg * 4 + tA + 1) ^ ks;
        *reinterpret_cast<uint32_t*>(smem + base + ch0 * 16 + ao) = f2h2(v.x, v.y);
        *reinterpret_cast<uint32_t*>(smem + base + ch1 * 16 + ao) = f2h2(v.z, v.w);
    }
    __syncthreads();

    if (warp < 8) {
        // ============ PRODUCER: MMA1 = X @ W1 (f16 accum), relu -> H =========
        // X A-frags for ks2 0..1 live in registers; ks2 2..3 loaded per chunk.
        uint32_t xf[2][4][4];
        #pragma unroll
        for (int mi = 0; mi < 2; ++mi)
            #pragma unroll
            for (int ks = 0; ks < 4; ++ks) {
                int rb = wr * 2 + mi;
                LDS128(xf[mi][ks],
                       sb + SM_X + (uint32_t)(((rb * 8 + ks) * 32 + (lane ^ ks)) * 16));
            }

        for (int c = 0; c < NCH; ++c) {
            const uint32_t wa = sb + ((c & 1) ? SM_WA1 : SM_WA0);
            const uint32_t hp = sb + ((c & 1) ? SM_H1 : SM_H0);

            CP_WAIT1();
            BAR_HALF(5);                         // W1_c visible to all producers
            if (c >= 2) BAR_SYNC(3 + (c & 1));   // H[c&1] consumed (chunk c-2)

            // two k=64 f16 segment accumulators per frag (seg = ks2>>1)
            uint32_t hacc[2][2][4][2];           // [seg][mi][nb][reg]
            #pragma unroll
            for (int sg = 0; sg < 2; ++sg)
                #pragma unroll
                for (int mi = 0; mi < 2; ++mi)
                    #pragma unroll
                    for (int nb = 0; nb < 4; ++nb) {
                        hacc[sg][mi][nb][0] = 0u;
                        hacc[sg][mi][nb][1] = 0u;
                    }

            #pragma unroll
            for (int ks2 = 0; ks2 < 4; ++ks2) {
                uint32_t ah[2][2][4];
                #pragma unroll
                for (int mi = 0; mi < 2; ++mi)
                    #pragma unroll
                    for (int kp = 0; kp < 2; ++kp) {
                        if (ks2 < 2) {
                            #pragma unroll
                            for (int e = 0; e < 4; ++e)
                                ah[mi][kp][e] = xf[mi][ks2 * 2 + kp][e];
                        } else {
                            int rb = wr * 2 + mi, ks = ks2 * 2 + kp;
                            LDS128(ah[mi][kp],
                                sb + SM_X + (uint32_t)(((rb * 8 + ks) * 32 + (lane ^ ks)) * 16));
                        }
                    }
                uint32_t bf[4][4];
                #pragma unroll
                for (int nb = 0; nb < 4; ++nb) {
                    int nbL = wc * 4 + nb;
                    LDS128(bf[nb], wa + (uint32_t)(((nbL * 4 + ks2) * 32 + lane) * 16));
                }
                if (ks2 < 2) burst1h(hacc[0], ah, bf);
                else         burst1h(hacc[1], ah, bf);
            }
            BAR_HALF(5);                 // all producers done reading WA[c&1]

            // prefetch W1_{c+2} into the WA buffer just freed
            if (c + 2 < NCH) {
                #pragma unroll
                for (int i = 0; i < 4; ++i) {
                    int s = tid + i * 256;
                    cp16(wa + s * 16, W1fb + (c + 2) * 16384 + s * 16);
                }
            }
            CP_COMMIT();

            // combine segments + bias + relu entirely in f16x2 -> MMA2 A-frags
            uint32_t aH[2][2][4];
            #pragma unroll
            for (int mi = 0; mi < 2; ++mi)
                #pragma unroll
                for (int ni = 0; ni < 4; ++ni) {
                    uint32_t bp = b1h2s[c * 32 + wc * 16 + ni * 4 + t];
                    uint32_t r0 = hmax2z(hadd2u(hadd2u(hacc[0][mi][ni][0],
                                                       hacc[1][mi][ni][0]), bp));
                    uint32_t r1 = hmax2z(hadd2u(hadd2u(hacc[0][mi][ni][1],
                                                       hacc[1][mi][ni][1]), bp));
                    int ksl = ni >> 1, off = (ni & 1) * 2;
                    aH[mi][ksl][off]     = r0;   // row g   half
                    aH[mi][ksl][off + 1] = r1;   // row g+8 half
                }
            #pragma unroll
            for (int mi = 0; mi < 2; ++mi)
                #pragma unroll
                for (int ksl = 0; ksl < 2; ++ksl) {
                    int rb = wr * 2 + mi, ksH = wc * 2 + ksl;
                    STS128(hp + (uint32_t)(((rb * 4 + ksH) * 32 + lane) * 16), aH[mi][ksl]);
                }
            BAR_ARRIVE(1 + (c & 1));     // H[c&1] full (release; no block)
        }
        // producers done; exit
    } else {
        // ================= CONSUMER: MMA2 = H @ W2 -> out (f32 accum) ========
        float acc2[2][8][4];
        #pragma unroll
        for (int mi = 0; mi < 2; ++mi)
            #pragma unroll
            for (int ni = 0; ni < 8; ++ni)
                #pragma unroll
                for (int e = 0; e < 4; ++e) acc2[mi][ni][e] = 0.0f;

        for (int c = 0; c < NCH; ++c) {
            const uint32_t wb = sb + ((c & 1) ? SM_WB1 : SM_WB0);
            const uint32_t hp = sb + ((c & 1) ? SM_H1 : SM_H0);

            CP_WAIT1();
            BAR_HALF(6);                 // W2_c visible to all consumers
            BAR_SYNC(1 + (c & 1));       // H[c&1] full

            #pragma unroll
            for (int ks2 = 0; ks2 < 2; ++ks2) {
                uint32_t hf[2][2][4];
                #pragma unroll
                for (int mi = 0; mi < 2; ++mi)
                    #pragma unroll
                    for (int kp = 0; kp < 2; ++kp) {
                        int rb = wr * 2 + mi, ksH = ks2 * 2 + kp;
                        LDS128(hf[mi][kp],
                               hp + (uint32_t)(((rb * 4 + ksH) * 32 + lane) * 16));
                    }
                #pragma unroll
                for (int h4 = 0; h4 < 2; ++h4) {
                    uint32_t bf[4][4];
                    #pragma unroll
                    for (int j = 0; j < 4; ++j) {
                        int nb = wc * 8 + h4 * 4 + j;
                        LDS128(bf[j], wb + (uint32_t)(((nb * 2 + ks2) * 32 + lane) * 16));
                    }
                    burst2(&acc2[0][h4 * 4], &acc2[1][h4 * 4], hf, bf);
                }
            }
            BAR_ARRIVE(3 + (c & 1));     // H[c&1] free (non-blocking release)
            BAR_HALF(6);                 // all consumers done reading WB[c&1]

            // prefetch W2_{c+2} into the WB buffer just freed
            if (c + 2 < NCH) {
                #pragma unroll
                for (int i = 0; i < 4; ++i) {
                    int s = (tid - 256) + i * 256;
                    int nb = s >> 6, r = s & 63;
                    cp16(wb + s * 16, W2fb + nb * 8192 + (c + 2) * 1024 + r * 16);
                }
            }
            CP_COMMIT();
        }

        // ---- epilogue: acc2 + b2 -> gmem ----
        #pragma unroll
        for (int mi = 0; mi < 2; ++mi)
            #pragma unroll
            for (int ni = 0; ni < 8; ++ni) {
                int r1 = t0 + wr * 32 + mi * 16 + g;
                int cg = wc * 64 + ni * 8 + 2 * t;
                float2 v01, v23;
                v01.x = acc2[mi][ni][0] + b2s[cg];
                v01.y = acc2[mi][ni][1] + b2s[cg + 1];
                v23.x = acc2[mi][ni][2] + b2s[cg];
                v23.y = acc2[mi][ni][3] + b2s[cg + 1];
                *reinterpret_cast<float2*>(out + (size_t)r1 * D_MODEL + head * HEAD_DIM + cg) = v01;
                *reinterpret_cast<float2*>(out + (size_t)(r1 + 8) * D_MODEL + head * HEAD_DIM + cg) = v23;
            }
    }
}

// -------------------------------------------------------------- launch ------
extern "C" void kernel_launch(void* const* d_in, const int* in_sizes, int n_in,
                              void* d_out, int out_size) {
    const float* x  = (const float*)d_in[0];
    const float* W1 = (const float*)d_in[1];
    const float* b1 = (const float*)d_in[2];
    const float* W2 = (const float*)d_in[3];
    const float* b2 = (const float*)d_in[4];
    float* out = (float*)d_out;

    frag_kernel<<<512, 256>>>(W1, W2);   // 131072 threads, one 16B block each

    cudaFuncSetAttribute(ffn_kernel, cudaFuncAttributeMaxDynamicSharedMemorySize, SMEM_TOTAL);
    ffn_kernel<<<dim3(16384 / TILE_M, N_HEADS), THREADS, SMEM_TOTAL>>>(x, b1, b2, out);
}

// round 17
// speedup vs baseline: 1.0042x; 1.0033x over previous
#include <cuda_runtime.h>
#include <cuda_fp16.h>
#include <cstdint>

#define N_HEADS   16
#define HEAD_DIM  128
#define FF_DIM    512
#define D_MODEL   2048
#define TILE_M    128
#define FFC       64
#define NCH       (FF_DIM / FFC)   // 8
#define THREADS   512

// fp16 weights in B-fragment-major order (built once per launch)
__device__ __half g_W1f[N_HEADS * HEAD_DIM * FF_DIM];   // 2 MB
__device__ __half g_W2f[N_HEADS * FF_DIM * HEAD_DIM];   // 2 MB

// --------------------------------------------------------- SMEM layout ------
static constexpr int SM_H0  = 0;        // 16384
static constexpr int SM_H1  = 16384;    // 16384
static constexpr int SM_X   = 32768;    // 32768
static constexpr int SM_WA0 = 65536;    // 16384
static constexpr int SM_WA1 = 81920;    // 16384
static constexpr int SM_WB0 = 98304;    // 16384
static constexpr int SM_WB1 = 114688;   // 16384
static constexpr int SM_B1  = 131072;   // 256 x f16x2 bias pairs (1 KB)
static constexpr int SM_B2  = 133120;   // 128 f32
static constexpr int SMEM_TOTAL = 133632;

// ---------------------------------------------------------------- helpers ---
__device__ __forceinline__ uint32_t smem_u32(const void* p) {
    uint32_t a;
    asm("{ .reg .u64 t; cvta.to.shared.u64 t, %1; cvt.u32.u64 %0, t; }" : "=r"(a) : "l"(p));
    return a;
}
__device__ __forceinline__ uint32_t f2h2(float lo, float hi) {
    uint32_t r;
    asm("cvt.rn.f16x2.f32 %0, %1, %2;" : "=r"(r) : "f"(hi), "f"(lo));
    return r;
}
__device__ __forceinline__ uint32_t hadd2u(uint32_t a, uint32_t b) {
    uint32_t r;
    asm("add.f16x2 %0, %1, %2;" : "=r"(r) : "r"(a), "r"(b));
    return r;
}
__device__ __forceinline__ uint32_t hmax2z(uint32_t a) {
    uint32_t r;
    asm("max.f16x2 %0, %1, %2;" : "=r"(r) : "r"(a), "r"(0u));
    return r;
}
__device__ __forceinline__ void cp16(uint32_t s, const void* g) {
    asm volatile("cp.async.ca.shared.global [%0], [%1], 16;" :: "r"(s), "l"(g));
}
#define CP_COMMIT() asm volatile("cp.async.commit_group;" ::: "memory")
#define CP_WAIT1()  asm volatile("cp.async.wait_group 1;" ::: "memory")

#define BAR_SYNC(id)   asm volatile("bar.sync %0, 512;"   :: "r"(id) : "memory")
#define BAR_ARRIVE(id) asm volatile("bar.arrive %0, 512;" :: "r"(id) : "memory")
#define BAR_HALF(id)   asm volatile("bar.sync %0, 256;"   :: "r"(id) : "memory")

#define LDS128(r, addr) \
    asm volatile("ld.shared.v4.b32 {%0,%1,%2,%3}, [%4];" \
        : "=r"((r)[0]), "=r"((r)[1]), "=r"((r)[2]), "=r"((r)[3]) : "r"(addr))
#define STS128(addr, r) \
    asm volatile("st.shared.v4.b32 [%0], {%1,%2,%3,%4};" \
        :: "r"(addr), "r"((r)[0]), "r"((r)[1]), "r"((r)[2]), "r"((r)[3]) : "memory")

// f32-accum MMA (consumer)
__device__ __forceinline__ void mma16816(float* d, const uint32_t* a, const uint32_t* b) {
    asm("mma.sync.aligned.m16n8k16.row.col.f32.f16.f16.f32 "
        "{%0,%1,%2,%3}, {%4,%5,%6,%7}, {%8,%9}, {%0,%1,%2,%3};"
        : "+f"(d[0]), "+f"(d[1]), "+f"(d[2]), "+f"(d[3])
        : "r"(a[0]), "r"(a[1]), "r"(a[2]), "r"(a[3]), "r"(b[0]), "r"(b[1]));
}
// f16-accum MMA (producer) — D/C are 2 regs of f16x2
__device__ __forceinline__ void mma16816h(uint32_t* d, const uint32_t* a, const uint32_t* b) {
    asm("mma.sync.aligned.m16n8k16.row.col.f16.f16.f16.f16 "
        "{%0,%1}, {%2,%3,%4,%5}, {%6,%7}, {%0,%1};"
        : "+r"(d[0]), "+r"(d[1])
        : "r"(a[0]), "r"(a[1]), "r"(a[2]), "r"(a[3]), "r"(b[0]), "r"(b[1]));
}

// f16 MMA burst: 16 MMAs, dep distance 8 (khalf-0 sweep, then khalf-1 sweep)
__device__ __forceinline__ void burst1h(uint32_t hacc[2][4][2],
                                        const uint32_t ah[2][2][4],
                                        const uint32_t bf[4][4]) {
    #pragma unroll
    for (int nb = 0; nb < 4; ++nb) mma16816h(hacc[0][nb], ah[0][0], bf[nb]);
    #pragma unroll
    for (int nb = 0; nb < 4; ++nb) mma16816h(hacc[1][nb], ah[1][0], bf[nb]);
    #pragma unroll
    for (int nb = 0; nb < 4; ++nb) mma16816h(hacc[0][nb], ah[0][1], bf[nb] + 2);
    #pragma unroll
    for (int nb = 0; nb < 4; ++nb) mma16816h(hacc[1][nb], ah[1][1], bf[nb] + 2);
}
__device__ __forceinline__ void burst2(float (*a0)[4], float (*a1)[4],
                                       const uint32_t hf[2][2][4],
                                       const uint32_t bf[4][4]) {
    #pragma unroll
    for (int j = 0; j < 4; ++j) mma16816(a0[j], hf[0][0], bf[j]);
    #pragma unroll
    for (int j = 0; j < 4; ++j) mma16816(a1[j], hf[1][0], bf[j]);
    #pragma unroll
    for (int j = 0; j < 4; ++j) mma16816(a0[j], hf[0][1], bf[j] + 2);
    #pragma unroll
    for (int j = 0; j < 4; ++j) mma16816(a1[j], hf[1][1], bf[j] + 2);
}

// ------------------------------ weight -> fp16 B-fragment-major rearrange ---
__global__ void frag_kernel(const float* __restrict__ w1, const float* __restrict__ w2) {
    int b = blockIdx.x * blockDim.x + threadIdx.x;   // 0 .. 131071
    {   // W1: src [head][d:128][f:512]
        int tt = b & 3, gg = (b >> 2) & 7, ks2 = (b >> 5) & 3;
        int nb = (b >> 7) & 63, head = b >> 13;
        const float* s = w1 + (size_t)head * 65536 + nb * 8 + gg;
        int dbase = ks2 * 32 + tt * 2;
        uint32_t u[4];
        #pragma unroll
        for (int j = 0; j < 4; ++j) {
            int d = dbase + (j >> 1) * 16 + (j & 1) * 8;
            u[j] = f2h2(s[(size_t)d * 512], s[(size_t)(d + 1) * 512]);
        }
        reinterpret_cast<uint4*>(g_W1f)[b] = make_uint4(u[0], u[1], u[2], u[3]);
    }
    {   // W2: src [head][f:512][d:128]
        int tt = b & 3, gg = (b >> 2) & 7, ks2 = (b >> 5) & 15;
        int nb = (b >> 9) & 15, head = b >> 13;
        const float* s = w2 + (size_t)head * 65536 + nb * 8 + gg;
        int fbase = ks2 * 32 + tt * 2;
        uint32_t u[4];
        #pragma unroll
        for (int j = 0; j < 4; ++j) {
            int f = fbase + (j >> 1) * 16 + (j & 1) * 8;
            u[j] = f2h2(s[(size_t)f * 128], s[(size_t)(f + 1) * 128]);
        }
        reinterpret_cast<uint4*>(g_W2f)[b] = make_uint4(u[0], u[1], u[2], u[3]);
    }
}

// ----------------------------------------------------------- main kernel ----
// Warps 0-7: producers (MMA1, f16 accum).  Warps 8-15: consumers (MMA2, f32).
// Barriers: 1/2 = H[p] full  (producer ARRIVE, consumer SYNC).
//           3/4 = H[p] free  (consumer ARRIVE, producer SYNC; skipped c<2).
//           5 = producer-only half.  6 = consumer-only half.
__global__ void __launch_bounds__(THREADS, 1)
ffn_kernel(const float* __restrict__ x, const float* __restrict__ b1,
           const float* __restrict__ b2, float* __restrict__ out) {
    extern __shared__ char smem[];
    const int tid  = threadIdx.x;
    const int lane = tid & 31;
    const int warp = tid >> 5;
    const int g    = lane >> 2;
    const int t    = lane & 3;
    const int w8   = warp & 7;
    const int wr   = w8 >> 1;        // 0..3 (32-row group)
    const int wc   = w8 & 1;         // 0..1 (col half)

    const int head = blockIdx.y;
    const int t0   = blockIdx.x * TILE_M;
    const uint32_t sb = smem_u32(smem);

    uint32_t* b1h2s = reinterpret_cast<uint32_t*>(smem + SM_B1);   // 256 f16x2 pairs
    float*    b2s   = reinterpret_cast<float*>(smem + SM_B2);

    const char* W1fb = (const char*)(g_W1f + (size_t)head * 65536);
    const char* W2fb = (const char*)(g_W2f + (size_t)head * 65536);

    // ---- prologue cp.async: producers load W1_0/W1_1, consumers W2_0/W2_1 ----
    if (warp < 8) {
        #pragma unroll
        for (int i = 0; i < 4; ++i) {
            int s = tid + i * 256;
            cp16(sb + SM_WA0 + s * 16, W1fb + s * 16);
        }
        CP_COMMIT();
        #pragma unroll
        for (int i = 0; i < 4; ++i) {
            int s = tid + i * 256;
            cp16(sb + SM_WA1 + s * 16, W1fb + 16384 + s * 16);
        }
        CP_COMMIT();
    } else {
        #pragma unroll
        for (int i = 0; i < 4; ++i) {
            int s = (tid - 256) + i * 256;
            int nb = s >> 6, r = s & 63;
            cp16(sb + SM_WB0 + s * 16, W2fb + nb * 8192 + r * 16);
        }
        CP_COMMIT();
        #pragma unroll
        for (int i = 0; i < 4; ++i) {
            int s = (tid - 256) + i * 256;
            int nb = s >> 6, r = s & 63;
            cp16(sb + SM_WB1 + s * 16, W2fb + nb * 8192 + 1024 + r * 16);
        }
        CP_COMMIT();
    }

    // ---- biases: b1 packed as f16x2 column pairs; b2 stays f32 ----
    if (tid < 256) {
        const float* bp = b1 + head * FF_DIM + 2 * tid;
        b1h2s[tid] = f2h2(bp[0], bp[1]);
    }
    if (tid < HEAD_DIM) b2s[tid] = b2[head * HEAD_DIM + tid];

    // ---- X tile: fp32 gmem -> fp16 A-fragment-major SMEM (persistent) ----
    #pragma unroll
    for (int i = 0; i < 8; ++i) {
        int u = tid + i * THREADS;            // 4096 float4 segs
        int row = u >> 5, c4 = (u & 31) << 2;
        float4 v = *reinterpret_cast<const float4*>(
            x + (size_t)(t0 + row) * D_MODEL + head * HEAD_DIM + c4);
        int rb = row >> 4, gg = row & 7, hm = (row >> 3) & 1;
        int ks = c4 >> 4, hk = (c4 >> 3) & 1, tA = (c4 & 7) >> 1;
        uint32_t base = (uint32_t)(SM_X + ((rb * 8 + ks) * 32) * 16);
        int ao = (hm * 2 + hk * 4) * 2;
        int ch0 = (gg * 4 + tA) ^ ks, ch1 = (gg * 4 + tA + 1) ^ ks;
        *reinterpret_cast<uint32_t*>(smem + base + ch0 * 16 + ao) = f2h2(v.x, v.y);
        *reinterpret_cast<uint32_t*>(smem + base + ch1 * 16 + ao) = f2h2(v.z, v.w);
    }
    __syncthreads();

    if (warp < 8) {
        // ============ PRODUCER: MMA1 = X @ W1 (f16 accum), relu -> H =========
        // X A-frags for ks2 0..1 live in registers; ks2 2..3 loaded per chunk.
        uint32_t xf[2][4][4];
        #pragma unroll
        for (int mi = 0; mi < 2; ++mi)
            #pragma unroll
            for (int ks = 0; ks < 4; ++ks) {
                int rb = wr * 2 + mi;
                LDS128(xf[mi][ks],
                       sb + SM_X + (uint32_t)(((rb * 8 + ks) * 32 + (lane ^ ks)) * 16));
            }

        for (int c = 0; c < NCH; ++c) {
            const uint32_t wa = sb + ((c & 1) ? SM_WA1 : SM_WA0);
            const uint32_t hp = sb + ((c & 1) ? SM_H1 : SM_H0);

            CP_WAIT1();
            BAR_HALF(5);                         // W1_c visible to all producers
            if (c >= 2) BAR_SYNC(3 + (c & 1));   // H[c&1] consumed (chunk c-2)

            // two k=64 f16 segment accumulators per frag (seg = ks2>>1)
            uint32_t hacc[2][2][4][2];           // [seg][mi][nb][reg]
            #pragma unroll
            for (int sg = 0; sg < 2; ++sg)
                #pragma unroll
                for (int mi = 0; mi < 2; ++mi)
                    #pragma unroll
                    for (int nb = 0; nb < 4; ++nb) {
                        hacc[sg][mi][nb][0] = 0u;
                        hacc[sg][mi][nb][1] = 0u;
                    }

            #pragma unroll
            for (int ks2 = 0; ks2 < 4; ++ks2) {
                uint32_t ah[2][2][4];
                #pragma unroll
                for (int mi = 0; mi < 2; ++mi)
                    #pragma unroll
                    for (int kp = 0; kp < 2; ++kp) {
                        if (ks2 < 2) {
                            #pragma unroll
                            for (int e = 0; e < 4; ++e)
                                ah[mi][kp][e] = xf[mi][ks2 * 2 + kp][e];
                        } else {
                            int rb = wr * 2 + mi, ks = ks2 * 2 + kp;
                            LDS128(ah[mi][kp],
                                sb + SM_X + (uint32_t)(((rb * 8 + ks) * 32 + (lane ^ ks)) * 16));
                        }
                    }
                uint32_t bf[4][4];
                #pragma unroll
                for (int nb = 0; nb < 4; ++nb) {
                    int nbL = wc * 4 + nb;
                    LDS128(bf[nb], wa + (uint32_t)(((nbL * 4 + ks2) * 32 + lane) * 16));
                }
                if (ks2 < 2) burst1h(hacc[0], ah, bf);
                else         burst1h(hacc[1], ah, bf);
            }
            BAR_HALF(5);                 // all producers done reading WA[c&1]

            // prefetch W1_{c+2} into the WA buffer just freed
            if (c + 2 < NCH) {
                #pragma unroll
                for (int i = 0; i < 4; ++i) {
                    int s = tid + i * 256;
                    cp16(wa + s * 16, W1fb + (c + 2) * 16384 + s * 16);
                }
            }
            CP_COMMIT();

            // combine segments + bias + relu entirely in f16x2 -> MMA2 A-frags
            uint32_t aH[2][2][4];
            #pragma unroll
            for (int mi = 0; mi < 2; ++mi)
                #pragma unroll
                for (int ni = 0; ni < 4; ++ni) {
                    uint32_t bp = b1h2s[c * 32 + wc * 16 + ni * 4 + t];
                    uint32_t r0 = hmax2z(hadd2u(hadd2u(hacc[0][mi][ni][0],
                                                       hacc[1][mi][ni][0]), bp));
                    uint32_t r1 = hmax2z(hadd2u(hadd2u(hacc[0][mi][ni][1],
                                                       hacc[1][mi][ni][1]), bp));
                    int ksl = ni >> 1, off = (ni & 1) * 2;
                    aH[mi][ksl][off]     = r0;   // row g   half
                    aH[mi][ksl][off + 1] = r1;   // row g+8 half
                }
            #pragma unroll
            for (int mi = 0; mi < 2; ++mi)
                #pragma unroll
                for (int ksl = 0; ksl < 2; ++ksl) {
                    int rb = wr * 2 + mi, ksH = wc * 2 + ksl;
                    STS128(hp + (uint32_t)(((rb * 4 + ksH) * 32 + lane) * 16), aH[mi][ksl]);
                }
            BAR_ARRIVE(1 + (c & 1));     // H[c&1] full (release; no block)
        }
        // producers done; exit
    } else {
        // ================= CONSUMER: MMA2 = H @ W2 -> out (f32 accum) ========
        float acc2[2][8][4];
        #pragma unroll
        for (int mi = 0; mi < 2; ++mi)
            #pragma unroll
            for (int ni = 0; ni < 8; ++ni)
                #pragma unroll
                for (int e = 0; e < 4; ++e) acc2[mi][ni][e] = 0.0f;

        for (int c = 0; c < NCH; ++c) {
            const uint32_t wb = sb + ((c & 1) ? SM_WB1 : SM_WB0);
            const uint32_t hp = sb + ((c & 1) ? SM_H1 : SM_H0);

            CP_WAIT1();
            BAR_HALF(6);                 // W2_c visible to all consumers
            BAR_SYNC(1 + (c & 1));       // H[c&1] full

            #pragma unroll
            for (int ks2 = 0; ks2 < 2; ++ks2) {
                uint32_t hf[2][2][4];
                #pragma unroll
                for (int mi = 0; mi < 2; ++mi)
                    #pragma unroll
                    for (int kp = 0; kp < 2; ++kp) {
                        int rb = wr * 2 + mi, ksH = ks2 * 2 + kp;
                        LDS128(hf[mi][kp],
                               hp + (uint32_t)(((rb * 4 + ksH) * 32 + lane) * 16));
                    }
                #pragma unroll
                for (int h4 = 0; h4 < 2; ++h4) {
                    uint32_t bf[4][4];
                    #pragma unroll
                    for (int j = 0; j < 4; ++j) {
                        int nb = wc * 8 + h4 * 4 + j;
                        LDS128(bf[j], wb + (uint32_t)(((nb * 2 + ks2) * 32 + lane) * 16));
                    }
                    burst2(&acc2[0][h4 * 4], &acc2[1][h4 * 4], hf, bf);
                }
            }
            BAR_ARRIVE(3 + (c & 1));     // H[c&1] free (non-blocking release)
            BAR_HALF(6);                 // all consumers done reading WB[c&1]

            // prefetch W2_{c+2} into the WB buffer just freed
            if (c + 2 < NCH) {
                #pragma unroll
                for (int i = 0; i < 4; ++i) {
                    int s = (tid - 256) + i * 256;
                    int nb = s >> 6, r = s & 63;
                    cp16(wb + s * 16, W2fb + nb * 8192 + (c + 2) * 1024 + r * 16);
                }
            }
            CP_COMMIT();
        }

        // ---- epilogue: acc2 + b2 -> gmem ----
        #pragma unroll
        for (int mi = 0; mi < 2; ++mi)
            #pragma unroll
            for (int ni = 0; ni < 8; ++ni) {
                int r1 = t0 + wr * 32 + mi * 16 + g;
                int cg = wc * 64 + ni * 8 + 2 * t;
                float2 v01, v23;
                v01.x = acc2[mi][ni][0] + b2s[cg];
                v01.y = acc2[mi][ni][1] + b2s[cg + 1];
                v23.x = acc2[mi][ni][2] + b2s[cg];
                v23.y = acc2[mi][ni][3] + b2s[cg + 1];
                *reinterpret_cast<float2*>(out + (size_t)r1 * D_MODEL + head * HEAD_DIM + cg) = v01;
                *reinterpret_cast<float2*>(out + (size_t)(r1 + 8) * D_MODEL + head * HEAD_DIM + cg) = v23;
            }
    }
}

// -------------------------------------------------------------- launch ------
extern "C" void kernel_launch(void* const* d_in, const int* in_sizes, int n_in,
                              void* d_out, int out_size) {
    const float* x  = (const float*)d_in[0];
    const float* W1 = (const float*)d_in[1];
    const float* b1 = (const float*)d_in[2];
    const float* W2 = (const float*)d_in[3];
    const float* b2 = (const float*)d_in[4];
    float* out = (float*)d_out;

    frag_kernel<<<512, 256>>>(W1, W2);   // 131072 threads, one 16B block each

    cudaFuncSetAttribute(ffn_kernel, cudaFuncAttributeMaxDynamicSharedMemorySize, SMEM_TOTAL);
    ffn_kernel<<<dim3(16384 / TILE_M, N_HEADS), THREADS, SMEM_TOTAL>>>(x, b1, b2, out);
}